// round 16
// baseline (speedup 1.0000x reference)
#include <cuda_runtime.h>
#include <cstdint>

// Problem constants
#define BATCH 16
#define SEQ   1024
#define F     256
#define MROWS (BATCH * SEQ)   // 16384

// Tile config
#define BM  128
#define BN  128
#define BK  32
#define BKP 36    // padded row stride (floats): conflict-free frags + 16B-aligned rows
#define NSPLIT 4  // split-K for k_tnM

// -------- scratch (no allocation allowed; __device__ globals) --------
__device__ float g_alpha[MROWS * F];
__device__ float g_beta [MROWS * F];
__device__ float g_unary[MROWS * F];
__device__ float g_part [NSPLIT * BATCH * F * F];   // split-K partials of Mt[b][f][h]
__device__ float g_Pt   [BATCH * F * F];            // Pt[b][g][h] = (1/N) sum_f Wr[g,f] Mt[b][f,h]
__device__ float g_d    [MROWS];

__device__ __forceinline__ uint32_t smem_u32(const void* p) {
    uint32_t a;
    asm("{ .reg .u64 t; cvta.to.shared.u64 t, %1; cvt.u32.u64 %0, t; }"
        : "=r"(a) : "l"(p));
    return a;
}

// fp32 -> tf32 bits (round-to-nearest) — register fill paths
__device__ __forceinline__ uint32_t tf32b(float x) {
    uint32_t r;
    asm("cvt.rna.tf32.f32 %0, %1;" : "=r"(r) : "f"(x));
    return r;
}

// ---------------- cp.async helpers ----------------
__device__ __forceinline__ void cp16(uint32_t dst, const void* src) {
    asm volatile("cp.async.cg.shared.global [%0], [%1], 16;" :: "r"(dst), "l"(src));
}
#define CP_COMMIT() asm volatile("cp.async.commit_group;" ::: "memory")
#define CP_WAIT(N)  asm volatile("cp.async.wait_group %0;" :: "n"(N) : "memory")

// K-major async fill: 256 threads cover 128 rows x 32 floats (16B each).
__device__ __forceinline__ void fill_k_async(uint32_t Sb, const float* __restrict__ src,
                                             int ld, int row0, int k0, int tid)
{
    const int kq = tid & 7;      // 16B chunk along k
    const int r0 = tid >> 3;     // 0..31
#pragma unroll
    for (int i = 0; i < 4; ++i) {
        int r = r0 + i * 32;
        cp16(Sb + (uint32_t)(r * BKP + kq * 4) * 4u,
             src + (size_t)(row0 + r) * ld + k0 + kq * 4);
    }
}

// ---------------- register fill helpers ----------------
// K-major register load/store (tf32-rounded)
__device__ __forceinline__ void ldk(uint4 w[4], const float* __restrict__ src,
                                    int ld, int row0, int k0, int tid)
{
    const int kq = tid & 7, r0 = tid >> 3;
#pragma unroll
    for (int i = 0; i < 4; ++i) {
        float4 v = *(const float4*)&src[(size_t)(row0 + r0 + 32 * i) * ld + k0 + kq * 4];
        w[i].x = tf32b(v.x); w[i].y = tf32b(v.y); w[i].z = tf32b(v.z); w[i].w = tf32b(v.w);
    }
}
// K-major register load with per-row scale (for v = -d*u/N)
__device__ __forceinline__ void ldv(uint4 w[4], const float* __restrict__ src,
                                    int ld, int row0, int k0, int tid, const float sc[4])
{
    const int kq = tid & 7, r0 = tid >> 3;
#pragma unroll
    for (int i = 0; i < 4; ++i) {
        float4 v = *(const float4*)&src[(size_t)(row0 + r0 + 32 * i) * ld + k0 + kq * 4];
        w[i].x = tf32b(v.x * sc[i]); w[i].y = tf32b(v.y * sc[i]);
        w[i].z = tf32b(v.z * sc[i]); w[i].w = tf32b(v.w * sc[i]);
    }
}
__device__ __forceinline__ void stk(uint32_t* S, const uint4 w[4], int tid)
{
    const int kq = tid & 7, r0 = tid >> 3;
#pragma unroll
    for (int i = 0; i < 4; ++i)
        *(uint4*)&S[(r0 + 32 * i) * BKP + kq * 4] = w[i];
}

// Transposed register fill: S[c][k] = src[(k0+k)*ld + c0 + c]
__device__ __forceinline__ void ldt(uint4 w[4], const float* __restrict__ src,
                                    int ld, int c0, int k0, int tid)
{
    const int c  = tid & 127;
    const int kh = (tid >> 7) * 16;
    const float* p = &src[(size_t)(k0 + kh) * ld + c0 + c];
#pragma unroll
    for (int q = 0; q < 4; ++q) {
        const float* pk = p + q * 4 * ld;
        w[q].x = tf32b(pk[0 * ld]); w[q].y = tf32b(pk[1 * ld]);
        w[q].z = tf32b(pk[2 * ld]); w[q].w = tf32b(pk[3 * ld]);
    }
}
// Transposed fill with 4-way split-K partial reduction:
// S[c][k] = sum_sp part[sp][b][k0+k][c0+c]   (fp32 sum, then round to tf32)
__device__ __forceinline__ void ldtr(uint4 w[4], int b, int c0, int k0, int tid)
{
    const int c  = tid & 127;
    const int kh = (tid >> 7) * 16;
    const size_t ss = (size_t)BATCH * F * F;
    const float* p0 = g_part + ((size_t)b * F + (k0 + kh)) * F + c0 + c;
#pragma unroll
    for (int q = 0; q < 4; ++q) {
        float v[4];
#pragma unroll
        for (int j = 0; j < 4; ++j) {
            const float* pf = p0 + (size_t)(q * 4 + j) * F;
            v[j] = (pf[0] + pf[ss]) + (pf[2 * ss] + pf[3 * ss]);
        }
        w[q].x = tf32b(v[0]); w[q].y = tf32b(v[1]);
        w[q].z = tf32b(v[2]); w[q].w = tf32b(v[3]);
    }
}
__device__ __forceinline__ void stt(uint32_t* S, const uint4 w[4], int tid)
{
    const int c  = tid & 127;
    const int kh = (tid >> 7) * 16;
#pragma unroll
    for (int q = 0; q < 4; ++q)
        *(uint4*)&S[c * BKP + kh + q * 4] = w[q];
}

// ============================================================================
// Warp-level tf32 MMA core: one 128x128x32 smem tile pair.
// 8 warps (wm 2 x wn 4); warp tile 64x32 = 4x4 m16n8k8 per k-step.
// ============================================================================
__device__ __forceinline__ void mma_core(const uint32_t* __restrict__ As,
                                         const uint32_t* __restrict__ Bs,
                                         float acc[4][4][4],
                                         int wm, int wn, int gid, int tig)
{
#pragma unroll
    for (int ks = 0; ks < 4; ++ks) {
        const int kb = ks * 8 + tig;
        uint32_t a[4][4], b[4][2];
#pragma unroll
        for (int mt = 0; mt < 4; ++mt) {
            const uint32_t* p = &As[(wm * 64 + mt * 16 + gid) * BKP + kb];
            a[mt][0] = p[0];
            a[mt][1] = p[8 * BKP];
            a[mt][2] = p[4];
            a[mt][3] = p[8 * BKP + 4];
        }
#pragma unroll
        for (int nt = 0; nt < 4; ++nt) {
            const uint32_t* p = &Bs[(wn * 32 + nt * 8 + gid) * BKP + kb];
            b[nt][0] = p[0];
            b[nt][1] = p[4];
        }
#pragma unroll
        for (int mt = 0; mt < 4; ++mt)
#pragma unroll
            for (int nt = 0; nt < 4; ++nt)
                asm volatile(
                    "mma.sync.aligned.m16n8k8.row.col.f32.tf32.tf32.f32 "
                    "{%0,%1,%2,%3}, {%4,%5,%6,%7}, {%8,%9}, {%0,%1,%2,%3};"
                    : "+f"(acc[mt][nt][0]), "+f"(acc[mt][nt][1]),
                      "+f"(acc[mt][nt][2]), "+f"(acc[mt][nt][3])
                    : "r"(a[mt][0]), "r"(a[mt][1]), "r"(a[mt][2]), "r"(a[mt][3]),
                      "r"(b[nt][0]), "r"(b[nt][1]));
    }
}

#define EPILOG_COORDS()                                         \
    const int r_ = m0 + wm * 64 + mt * 16 + gid;                \
    const int c_ = n0 + wn * 32 + nt * 8 + 2 * tig;

// Pipelined K-major mainloop over NK chunks (both operands K-major, cp.async).
#define PIPELINED_LOOP(Asrc, Bsrc, arow0, brow0, NK)                         \
    fill_k_async(aAddr[0], Asrc, F, arow0, 0, tid);                          \
    fill_k_async(bAddr[0], Bsrc, F, brow0, 0, tid);                          \
    CP_COMMIT();                                                             \
    for (int i = 0; i < (NK); ++i) {                                         \
        if (i + 1 < (NK)) {                                                  \
            int st = (i + 1) & 1;                                            \
            fill_k_async(aAddr[st], Asrc, F, arow0, (i + 1) * BK, tid);      \
            fill_k_async(bAddr[st], Bsrc, F, brow0, (i + 1) * BK, tid);      \
            CP_COMMIT();                                                     \
            CP_WAIT(1);                                                      \
        } else {                                                             \
            CP_WAIT(0);                                                      \
        }                                                                    \
        __syncthreads();                                                     \
        mma_core(As[i & 1], Bs[i & 1], acc, wm, wn, gid, tig);               \
        __syncthreads();                                                     \
    }

// ============================================================================
// Kernel 1: NT GEMM  O[m,g] = sum_k X[m,k]*W[g,k]  (+bias when z==2)
// ============================================================================
__global__ __launch_bounds__(256, 2) void k_nt3(
    const float* __restrict__ X,
    const float* __restrict__ W0, const float* __restrict__ W1,
    const float* __restrict__ W2, const float* __restrict__ bias)
{
    __shared__ uint32_t As[2][BM * BKP];
    __shared__ uint32_t Bs[2][BN * BKP];

    const int z = blockIdx.z;
    const float* __restrict__ W = (z == 0) ? W0 : (z == 1) ? W1 : W2;
    float* __restrict__ O = (z == 0) ? g_alpha : (z == 1) ? g_beta : g_unary;

    const int tid = threadIdx.x, lane = tid & 31, wid = tid >> 5;
    const int wm = wid & 1, wn = wid >> 1;
    const int gid = lane >> 2, tig = lane & 3;
    const int m0 = blockIdx.y * BM, n0 = blockIdx.x * BN;
    const uint32_t aAddr[2] = {smem_u32(As[0]), smem_u32(As[1])};
    const uint32_t bAddr[2] = {smem_u32(Bs[0]), smem_u32(Bs[1])};

    float acc[4][4][4] = {};
    PIPELINED_LOOP(X, W, m0, n0, F / BK)

#pragma unroll
    for (int mt = 0; mt < 4; ++mt)
#pragma unroll
        for (int nt = 0; nt < 4; ++nt) {
            EPILOG_COORDS()
            float2 b2 = make_float2(0.f, 0.f);
            if (z == 2) b2 = *(const float2*)&bias[c_];
            *(float2*)&O[r_ * F + c_] =
                make_float2(acc[mt][nt][0] + b2.x, acc[mt][nt][1] + b2.y);
            *(float2*)&O[(r_ + 8) * F + c_] =
                make_float2(acc[mt][nt][2] + b2.x, acc[mt][nt][3] + b2.y);
        }
}

// ============================================================================
// Kernel 2: per-row dot  d[m] = alpha[m,:].beta[m,:]
// ============================================================================
__global__ __launch_bounds__(256) void dot_ab()
{
    int row = blockIdx.x * 8 + (threadIdx.x >> 5);
    int lane = threadIdx.x & 31;
    const float4* a = (const float4*)&g_alpha[row * F];
    const float4* b = (const float4*)&g_beta[row * F];
    float s = 0.f;
#pragma unroll
    for (int i = lane; i < F / 4; i += 32) {
        float4 av = a[i], bv = b[i];
        s += av.x * bv.x + av.y * bv.y + av.z * bv.z + av.w * bv.w;
    }
#pragma unroll
    for (int off = 16; off > 0; off >>= 1)
        s += __shfl_xor_sync(0xffffffffu, s, off);
    if (lane == 0) g_d[row] = s;
}

// ============================================================================
// Kernel 3: per-batch TN GEMM split-K:
//   part[sp][b][f][h] = sum_{n in split sp} unary[b,n,f]*beta[b,n,h]
// grid (2, 2, BATCH*NSPLIT). Register-prefetch double buffered.
// ============================================================================
__global__ __launch_bounds__(256) void k_tnM()
{
    __shared__ uint32_t As[BM * BKP];
    __shared__ uint32_t Bs[BN * BKP];

    const int b  = blockIdx.z >> 2;
    const int sp = blockIdx.z & 3;
    const float* __restrict__ U  = g_unary + (size_t)b * SEQ * F;
    const float* __restrict__ Bt = g_beta  + (size_t)b * SEQ * F;
    float* __restrict__ O = g_part + ((size_t)sp * BATCH + b) * F * F;

    const int tid = threadIdx.x, lane = tid & 31, wid = tid >> 5;
    const int wm = wid & 1, wn = wid >> 1;
    const int gid = lane >> 2, tig = lane & 3;
    const int m0 = blockIdx.y * BM, n0 = blockIdx.x * BN;   // m0 = f, n0 = h
    const int k00 = sp * (SEQ / NSPLIT);
    const int NK = (SEQ / NSPLIT) / BK;   // 8

    float acc[4][4][4] = {};
    uint4 wa[4], wb[4];
    ldt(wa, U,  F, m0, k00, tid);
    ldt(wb, Bt, F, n0, k00, tid);

    for (int i = 0; i < NK; ++i) {
        stt(As, wa, tid);
        stt(Bs, wb, tid);
        __syncthreads();
        if (i + 1 < NK) {
            ldt(wa, U,  F, m0, k00 + (i + 1) * BK, tid);
            ldt(wb, Bt, F, n0, k00 + (i + 1) * BK, tid);
        }
        mma_core(As, Bs, acc, wm, wn, gid, tig);
        __syncthreads();
    }

#pragma unroll
    for (int mt = 0; mt < 4; ++mt)
#pragma unroll
        for (int nt = 0; nt < 4; ++nt) {
            EPILOG_COORDS()
            *(float2*)&O[r_ * F + c_]       = make_float2(acc[mt][nt][0], acc[mt][nt][1]);
            *(float2*)&O[(r_ + 8) * F + c_] = make_float2(acc[mt][nt][2], acc[mt][nt][3]);
        }
}

// ============================================================================
// Kernel 4: per-batch  Pt[b][g,h] = (1/N) * sum_f Wr[g,f] * Mt[b][f,h],
// where Mt[b][f,h] = sum_sp part[sp][b][f][h] (reduced inside the B fill).
// grid (2, 2, BATCH): m = g (A = Wr, K-major), n = h (B = Mt^T, transposed+reduce).
// ============================================================================
__global__ __launch_bounds__(256) void k_P(const float* __restrict__ Wr)
{
    __shared__ uint32_t As[BM * BKP];
    __shared__ uint32_t Bs[BN * BKP];

    const int b = blockIdx.z;
    float* __restrict__ O = g_Pt + (size_t)b * F * F;

    const int tid = threadIdx.x, lane = tid & 31, wid = tid >> 5;
    const int wm = wid & 1, wn = wid >> 1;
    const int gid = lane >> 2, tig = lane & 3;
    const int m0 = blockIdx.y * BM, n0 = blockIdx.x * BN;   // m0 = g, n0 = h
    const int NK = F / BK;   // 8

    float acc[4][4][4] = {};
    uint4 wa[4], wb[4];
    ldk (wa, Wr, F, m0, 0, tid);
    ldtr(wb, b, n0, 0, tid);

    for (int i = 0; i < NK; ++i) {
        stk(As, wa, tid);
        stt(Bs, wb, tid);
        __syncthreads();
        if (i + 1 < NK) {
            ldk (wa, Wr, F, m0, (i + 1) * BK, tid);
            ldtr(wb, b, n0, (i + 1) * BK, tid);
        }
        mma_core(As, Bs, acc, wm, wn, gid, tig);
        __syncthreads();
    }

    const float invN = 1.0f / (float)SEQ;
#pragma unroll
    for (int mt = 0; mt < 4; ++mt)
#pragma unroll
        for (int nt = 0; nt < 4; ++nt) {
            EPILOG_COORDS()
            *(float2*)&O[r_ * F + c_] =
                make_float2(acc[mt][nt][0] * invN, acc[mt][nt][1] * invN);
            *(float2*)&O[(r_ + 8) * F + c_] =
                make_float2(acc[mt][nt][2] * invN, acc[mt][nt][3] * invN);
        }
}

// ============================================================================
// Kernel 5 (fused): out[m,g] = sum_h alpha[m,h]*Pt[b][g,h]
//                            + sum_f v[m,f]*Wr[g,f] + x[m,g],
// with v[m,f] = -d[m]*u[m,f]/N. Phase A: cp.async pipelined (alpha x Pt).
// Phase B: register-prefetch (v x Wr) accumulating into the same acc.
// ============================================================================
__global__ __launch_bounds__(256, 2) void k_fused(
    const float* __restrict__ Wr, const float* __restrict__ X,
    float* __restrict__ out)
{
    __shared__ uint32_t As[2][BM * BKP];
    __shared__ uint32_t Bs[2][BN * BKP];

    const int tid = threadIdx.x, lane = tid & 31, wid = tid >> 5;
    const int wm = wid & 1, wn = wid >> 1;
    const int gid = lane >> 2, tig = lane & 3;
    const int m0 = blockIdx.y * BM, n0 = blockIdx.x * BN;
    const int b = m0 >> 10;
    const float* __restrict__ Ptb = g_Pt + (size_t)b * F * F;
    const uint32_t aAddr[2] = {smem_u32(As[0]), smem_u32(As[1])};
    const uint32_t bAddr[2] = {smem_u32(Bs[0]), smem_u32(Bs[1])};

    float acc[4][4][4] = {};

    // ---- Phase A: alpha x Pt (K = 256 over h), cp.async pipelined ----
    PIPELINED_LOOP(g_alpha, Ptb, m0, n0, F / BK)

    // ---- Phase B: v x Wr (K = 256 over f), register double-buffered ----
    const float invN = 1.0f / (float)SEQ;
    float sc[4];
    {
        const int r0 = tid >> 3;
#pragma unroll
        for (int i = 0; i < 4; ++i)
            sc[i] = -g_d[m0 + r0 + 32 * i] * invN;
    }
    uint4 wa[4], wb[4];
    ldv(wa, g_unary, F, m0, 0, tid, sc);
    ldk(wb, Wr, F, n0, 0, tid);
    for (int i = 0; i < F / BK; ++i) {
        stk(As[0], wa, tid);
        stk(Bs[0], wb, tid);
        __syncthreads();
        if (i + 1 < F / BK) {
            ldv(wa, g_unary, F, m0, (i + 1) * BK, tid, sc);
            ldk(wb, Wr, F, n0, (i + 1) * BK, tid);
        }
        mma_core(As[0], Bs[0], acc, wm, wn, gid, tig);
        __syncthreads();
    }

    // ---- Epilogue: + x ----
#pragma unroll
    for (int mt = 0; mt < 4; ++mt)
#pragma unroll
        for (int nt = 0; nt < 4; ++nt) {
            EPILOG_COORDS()
            float2 x0 = *(const float2*)&X[r_ * F + c_];
            float2 x1 = *(const float2*)&X[(r_ + 8) * F + c_];
            *(float2*)&out[r_ * F + c_] =
                make_float2(acc[mt][nt][0] + x0.x, acc[mt][nt][1] + x0.y);
            *(float2*)&out[(r_ + 8) * F + c_] =
                make_float2(acc[mt][nt][2] + x1.x, acc[mt][nt][3] + x1.y);
        }
}

// ============================================================================
// Launch
// ============================================================================
extern "C" void kernel_launch(void* const* d_in, const int* in_sizes, int n_in,
                              void* d_out, int out_size)
{
    const float* x  = (const float*)d_in[0];
    const float* Wa = (const float*)d_in[1];
    const float* Wb = (const float*)d_in[2];
    const float* Wu = (const float*)d_in[3];
    const float* bu = (const float*)d_in[4];
    const float* Wr = (const float*)d_in[5];
    float* out = (float*)d_out;

    k_nt3  <<<dim3(F / BN, MROWS / BM, 3), 256>>>(x, Wa, Wb, Wu, bu);
    dot_ab <<<MROWS / 8, 256>>>();
    k_tnM  <<<dim3(F / BN, F / BM, BATCH * NSPLIT), 256>>>();
    k_P    <<<dim3(F / BN, F / BM, BATCH), 256>>>(Wr);
    k_fused<<<dim3(F / BN, MROWS / BM), 256>>>(Wr, x, out);
}